// round 13
// baseline (speedup 1.0000x reference)
#include <cuda_runtime.h>
#include <math.h>

#define NB 64
#define TIN 1000
#define CIN 4
#define FEAT 320
#define KW 26
#define POOLW 13
#define TPOOL 75
#define HU 320
#define H3 960
#define FLATN 48000
#define ND1 2000
#define ND2 301
#define KSPLIT 50
#define KSEG (FLATN / KSPLIT)   /* 960 */

/* GRU v7: 32 CTAs per dir, 10 units each, hierarchical barrier */
#define GB2 32
#define JPC 10
#define PRE_OFF (HU*64)
#define GRU7_SMEM ((HU*64 + 4*32*66) * 4)

#define XSTR 1032

__device__ float g_pooled[NB*TPOOL*FEAT];
__device__ float g_xp[2][TPOOL*H3*NB];
__device__ float g_y[FLATN*NB];
__device__ __align__(128) float g_htf[2][2][HU*NB];
__device__ float g_part[KSPLIT][NB*ND1];
__device__ float g_hidden[NB*ND1];
__device__ unsigned g_cntg[2][8];     /* group counters (4 CTAs each) */
__device__ unsigned g_cnt2[2];        /* super counter (8 groups) */
__device__ unsigned g_gen2[2];

__device__ __forceinline__ float sigf(float x) { return 1.0f / (1.0f + __expf(-x)); }

__device__ __forceinline__ void cp16(const void* dst, const void* src) {
    unsigned d = (unsigned)__cvta_generic_to_shared(dst);
    asm volatile("cp.async.cg.shared.global [%0], [%1], 16;\n" :: "r"(d), "l"(src));
}
__device__ __forceinline__ void cpcommit() { asm volatile("cp.async.commit_group;\n" ::); }
__device__ __forceinline__ void cpwait0()  { asm volatile("cp.async.wait_group 0;\n" ::); }
__device__ __forceinline__ void cpwait2()  { asm volatile("cp.async.wait_group 2;\n" ::); }
__device__ __forceinline__ unsigned tf32r(float x) {
    unsigned r; asm("cvt.rna.tf32.f32 %0, %1;\n" : "=r"(r) : "f"(x)); return r;
}
__device__ __forceinline__ void mma8(float* c, const unsigned* a, const unsigned* b) {
    asm volatile(
        "mma.sync.aligned.m16n8k8.row.col.f32.tf32.tf32.f32 "
        "{%0,%1,%2,%3},{%4,%5,%6,%7},{%8,%9},{%0,%1,%2,%3};\n"
        : "+f"(c[0]), "+f"(c[1]), "+f"(c[2]), "+f"(c[3])
        : "r"(a[0]), "r"(a[1]), "r"(a[2]), "r"(a[3]), "r"(b[0]), "r"(b[1]));
}
__device__ __forceinline__ int swz(int k, int m) { return k*64 + (m ^ ((k & 3) * 8)); }

/* -------- conv1d + relu + maxpool13 via tf32 MMA (implicit im2col) ------- */
__global__ void __launch_bounds__(256) conv_mma(const float* __restrict__ in,
                                                const float* __restrict__ cw,
                                                const float* __restrict__ cb)
{
    __shared__ __align__(16) float xs[CIN*XSTR];
    __shared__ __align__(16) float Ws[KW*CIN*72];
    int b = blockIdx.y, n0 = blockIdx.x * 64, tid = threadIdx.x;

    for (int i = tid; i < 104*16; i += 256) {
        int kc = i >> 4, nq = (i & 15) * 4;
        cp16(&Ws[kc*72 + nq], &cw[kc*FEAT + n0 + nq]);
    }
    for (int i = tid; i < TIN*CIN; i += 256)
        xs[(i & 3)*XSTR + (i >> 2)] = in[b*TIN*CIN + i];
    if (tid < 4*32) {
        int c = tid >> 5, t = TIN + (tid & 31);
        if (t < XSTR) xs[c*XSTR + t] = 0.f;
    }
    cpcommit(); cpwait0();
    __syncthreads();

    int warp = tid >> 5, lane = tid & 31, g = lane >> 2, tg = lane & 3;
    bool row2ok = (g + 8) < POOLW;

    for (int tp = warp; tp < TPOOL; tp += 8) {
        int t0 = tp * POOLW;
        float c[8][4] = {};
        const float* xrow = &xs[tg*XSTR + t0 + g];
        #pragma unroll
        for (int ks = 0; ks < 13; ks++) {
            unsigned a[4];
            a[0] = tf32r(xrow[2*ks]);
            a[1] = tf32r(xrow[8 + 2*ks]);
            a[2] = tf32r(xrow[2*ks + 1]);
            a[3] = tf32r(xrow[8 + 2*ks + 1]);
            int kk = ks * 8;
            #pragma unroll
            for (int nf = 0; nf < 8; nf++) {
                unsigned bb[2];
                bb[0] = tf32r(Ws[(kk + tg    )*72 + nf*8 + g]);
                bb[1] = tf32r(Ws[(kk + tg + 4)*72 + nf*8 + g]);
                mma8(c[nf], a, bb);
            }
        }
        #pragma unroll
        for (int nf = 0; nf < 8; nf++) {
            float m0 = row2ok ? fmaxf(c[nf][0], c[nf][2]) : c[nf][0];
            float m1 = row2ok ? fmaxf(c[nf][1], c[nf][3]) : c[nf][1];
            #pragma unroll
            for (int off = 4; off < 32; off <<= 1) {
                m0 = fmaxf(m0, __shfl_xor_sync(0xffffffffu, m0, off));
                m1 = fmaxf(m1, __shfl_xor_sync(0xffffffffu, m1, off));
            }
            if (g == 0) {
                int col = n0 + nf*8 + tg*2;
                g_pooled[(b*TPOOL + tp)*FEAT + col]     = fmaxf(m0 + cb[col], 0.f);
                g_pooled[(b*TPOOL + tp)*FEAT + col + 1] = fmaxf(m1 + cb[col + 1], 0.f);
            }
        }
    }
}

/* ------- xproj via tf32 MMA ------- */
__global__ void __launch_bounds__(256) xproj_mma(const float* __restrict__ fwk,
                                                 const float* __restrict__ bwk,
                                                 const float* __restrict__ fwb,
                                                 const float* __restrict__ bwb)
{
    __shared__ __align__(16) float As[2][64][20];
    __shared__ __align__(16) float Ws[2][16][72];
    int m0 = blockIdx.x * 64, n0 = blockIdx.y * 64, dir = blockIdx.z;
    const float* Bk   = dir ? bwk : fwk;
    const float* bias = dir ? bwb : fwb;
    float* xp = g_xp[dir];

    int tid = threadIdx.x, warp = tid >> 5, lane = tid & 31;
    int g = lane >> 2, tg = lane & 3;
    int wm = (warp >> 2) * 32, wn = (warp & 3) * 16;
    int a_m = tid >> 2, a_k = (tid & 3) * 4;
    int w_k = tid >> 4, w_n = (tid & 15) * 4;

    float c[2][2][4] = {};

    cp16(&As[0][a_m][a_k], &g_pooled[(m0 + a_m)*FEAT + a_k]);
    cp16(&Ws[0][w_k][w_n], &Bk[w_k*H3 + n0 + w_n]);
    cpcommit();

    const int NIT = FEAT / 16;
    for (int it = 0; it < NIT; it++) {
        int nb = (it + 1) & 1;
        if (it + 1 < NIT) {
            int k0 = (it + 1) * 16;
            cp16(&As[nb][a_m][a_k], &g_pooled[(m0 + a_m)*FEAT + k0 + a_k]);
            cp16(&Ws[nb][w_k][w_n], &Bk[(k0 + w_k)*H3 + n0 + w_n]);
        }
        cpcommit();
        asm volatile("cp.async.wait_group 1;\n" ::);
        __syncthreads();
        int bf = it & 1;
        #pragma unroll
        for (int kh = 0; kh < 2; kh++) {
            int kk = kh * 8;
            unsigned a[2][4], b[2][2];
            #pragma unroll
            for (int mf = 0; mf < 2; mf++) {
                int m = wm + mf*16 + g;
                a[mf][0] = tf32r(As[bf][m    ][kk + tg]);
                a[mf][1] = tf32r(As[bf][m + 8][kk + tg]);
                a[mf][2] = tf32r(As[bf][m    ][kk + tg + 4]);
                a[mf][3] = tf32r(As[bf][m + 8][kk + tg + 4]);
            }
            #pragma unroll
            for (int nf = 0; nf < 2; nf++) {
                int n = wn + nf*8 + g;
                b[nf][0] = tf32r(Ws[bf][kk + tg    ][n]);
                b[nf][1] = tf32r(Ws[bf][kk + tg + 4][n]);
            }
            #pragma unroll
            for (int mf = 0; mf < 2; mf++)
                #pragma unroll
                for (int nf = 0; nf < 2; nf++)
                    mma8(c[mf][nf], a[mf], b[nf]);
        }
        __syncthreads();
    }

    #pragma unroll
    for (int mf = 0; mf < 2; mf++) {
        #pragma unroll
        for (int nf = 0; nf < 2; nf++) {
            int col = n0 + wn + nf*8 + tg*2;
            float bv0 = bias[col], bv1 = bias[col + 1];
            int r0 = m0 + wm + mf*16 + g;
            int b0 = r0 / TPOOL, t0 = r0 - b0*TPOOL;
            int r1 = r0 + 8;
            int b1 = r1 / TPOOL, t1 = r1 - b1*TPOOL;
            xp[(t0*H3 + col    )*NB + b0] = c[mf][nf][0] + bv0;
            xp[(t0*H3 + col + 1)*NB + b0] = c[mf][nf][1] + bv1;
            xp[(t1*H3 + col    )*NB + b1] = c[mf][nf][2] + bv0;
            xp[(t1*H3 + col + 1)*NB + b1] = c[mf][nf][3] + bv1;
        }
    }
}

/* --- persistent GRU v7: pair-local staging + hierarchical barrier -------- */
__global__ void __launch_bounds__(256, 1) gru7_kernel(
    const float* __restrict__ rk_fw, const float* __restrict__ rk_bw,
    const float* __restrict__ b_fw,  const float* __restrict__ b_bw)
{
    extern __shared__ float smg[];
    float* hs  = smg;                 /* [320][64] tf32 bits, swizzled */
    float* pre = smg + PRE_OFF;       /* [4][32][66] fp32 partials */

    int bx = blockIdx.x, dir = bx >> 5, jb = bx & 31, j0 = jb * JPC;
    const float* rk = dir ? rk_bw : rk_fw;
    const float* br = (dir ? b_bw : b_fw) + H3;
    const float* xp = g_xp[dir];
    int tid = threadIdx.x, warp = tid >> 5, lane = tid & 31;
    int g = lane >> 2, tg = lane & 3;
    int nw  = (warp & 1) * 16;
    int khq = warp >> 1;              /* pair id 0..3 = k quarter */
    int kh  = khq * 80;
    int pt  = tid & 63;               /* thread in pair */

    for (int i = tid; i < HU*64; i += 256) {
        int k = i >> 6, c = i & 63;
        float v = 0.f;
        if (c < 30) {
            int gi = c / JPC, jj = c - gi*JPC;
            v = rk[k*H3 + gi*HU + j0 + jj];
        }
        hs[swz(k, c)] = __uint_as_float(tf32r(v));
    }
    __syncthreads();

    const unsigned* hsu = (const unsigned*)hs;
    unsigned Bf[10][2][2];
    #pragma unroll
    for (int ks = 0; ks < 10; ks++) {
        int kk = kh + ks*8;
        #pragma unroll
        for (int nf = 0; nf < 2; nf++) {
            int n = nw + nf*8 + g;
            Bf[ks][nf][0] = hsu[swz(kk + tg,     n)];
            Bf[ks][nf][1] = hsu[swz(kk + tg + 4, n)];
        }
    }
    __syncthreads();

    int b = tid & 63, jq = tid >> 6;
    int nj = (jq < 2) ? 3 : 2;
    float hold[3] = {0.f, 0.f, 0.f};
    float brz[3], brr[3], brh[3];
    #pragma unroll
    for (int i = 0; i < 3; i++) {
        int jl = jq + 4*i;
        int jg = j0 + ((jl < JPC) ? jl : 0);
        brz[i] = br[jg]; brr[i] = br[HU + jg]; brh[i] = br[2*HU + jg];
    }

    float* buf0 = g_htf[dir][0];
    float* buf1 = g_htf[dir][1];

    float mzp[3], mrp[3], mhp[3];
    {
        int tt0 = dir ? (TPOOL - 1) : 0;
        #pragma unroll
        for (int i = 0; i < 3; i++) {
            int jl = jq + 4*i, jg = j0 + ((jl < JPC) ? jl : 0);
            mzp[i] = xp[(tt0*H3 + jg)*NB + b];
            mrp[i] = xp[(tt0*H3 + HU + jg)*NB + b];
            mhp[i] = xp[(tt0*H3 + 2*HU + jg)*NB + b];
        }
    }
    unsigned mygen = 0;
    unsigned hbv[3] = {0u, 0u, 0u};

    for (int s = 0; s < TPOOL; s++) {
        int tt = dir ? (TPOOL - 1 - s) : s;

        if (s > 0) {
            if (tid == 0) {
                while (*((volatile unsigned*)&g_gen2[dir]) == mygen) { }
            }
            __syncthreads();

            /* pair-local staging: each 64-thread pair stages its own quarter */
            {
                const float4* src = (const float4*)((s & 1) ? buf0 : buf1);
                float4* hs4 = (float4*)hs;
                int base = khq * 1280;   /* jq==khq for matching threads */
                #pragma unroll
                for (int i = 0; i < 20; i++)
                    cp16(&hs4[base + pt + i*64], &src[base + pt + i*64]);
                cpcommit();
                cpwait0();
                asm volatile("bar.sync %0, 64;\n" :: "r"(1 + khq) : "memory");
            }

            float c[4][2][4] = {};
            #pragma unroll
            for (int ks = 0; ks < 10; ks++) {
                int kk = kh + ks*8;
                unsigned a[4][4];
                #pragma unroll
                for (int mt = 0; mt < 4; mt++) {
                    int m = mt*16;
                    a[mt][0] = hsu[swz(kk + tg,     m + g)];
                    a[mt][1] = hsu[swz(kk + tg,     m + 8 + g)];
                    a[mt][2] = hsu[swz(kk + tg + 4, m + g)];
                    a[mt][3] = hsu[swz(kk + tg + 4, m + 8 + g)];
                }
                #pragma unroll
                for (int mt = 0; mt < 4; mt++)
                    #pragma unroll
                    for (int nf = 0; nf < 2; nf++)
                        mma8(c[mt][nf], a[mt], Bf[ks][nf]);
            }
            float* pb = pre + khq*32*66;
            #pragma unroll
            for (int mt = 0; mt < 4; mt++) {
                #pragma unroll
                for (int nf = 0; nf < 2; nf++) {
                    int n = nw + nf*8 + tg*2;
                    int m = mt*16 + g;
                    pb[(n    )*66 + m]     = c[mt][nf][0];
                    pb[(n + 1)*66 + m]     = c[mt][nf][1];
                    pb[(n    )*66 + m + 8] = c[mt][nf][2];
                    pb[(n + 1)*66 + m + 8] = c[mt][nf][3];
                }
            }
            __syncthreads();
        }

        float* wb = (s & 1) ? buf1 : buf0;
        #pragma unroll
        for (int i = 0; i < 3; i++) {
            if (i >= nj) break;
            int jl = jq + 4*i, jg = j0 + jl;
            float az = 0.f, ar = 0.f, ah = 0.f;
            if (s > 0) {
                #pragma unroll
                for (int p = 0; p < 4; p++) {
                    const float* pb = pre + p*32*66;
                    az += pb[(jl        )*66 + b];
                    ar += pb[(JPC + jl  )*66 + b];
                    ah += pb[(2*JPC + jl)*66 + b];
                }
            }
            float z    = sigf(mzp[i] + az + brz[i]);
            float r    = sigf(mrp[i] + ar + brr[i]);
            float cand = tanhf(mhp[i] + r * (ah + brh[i]));
            float hn   = z * hold[i] + (1.f - z) * cand;
            hold[i] = hn;
            hbv[i] = tf32r(hn);
            wb[swz(jg, b)] = __uint_as_float(hbv[i]);
        }

        if (s < TPOOL - 1) {
            __threadfence();
            __syncthreads();
            if (tid == 0) {
                mygen = *((volatile unsigned*)&g_gen2[dir]);
                unsigned r = atomicAdd(&g_cntg[dir][jb & 7], 1u);
                if (r == 3u) {
                    unsigned r2 = atomicAdd(&g_cnt2[dir], 1u);
                    if (r2 == 7u) {
                        g_cnt2[dir] = 0u;
                        #pragma unroll
                        for (int i = 0; i < 8; i++) g_cntg[dir][i] = 0u;
                        __threadfence();
                        atomicAdd(&g_gen2[dir], 1u);
                    }
                }
            }
            /* overlap spin: g_y writes + next-step gate prefetch */
            #pragma unroll
            for (int i = 0; i < 3; i++) {
                if (i >= nj) break;
                int jg = j0 + jq + 4*i;
                g_y[((tt*2 + dir)*HU + jg)*NB + b] = __uint_as_float(hbv[i]);
            }
            int tn = dir ? (TPOOL - 2 - s) : (s + 1);
            #pragma unroll
            for (int i = 0; i < 3; i++) {
                int jl = jq + 4*i, jg = j0 + ((jl < JPC) ? jl : 0);
                mzp[i] = xp[(tn*H3 + jg)*NB + b];
                mrp[i] = xp[(tn*H3 + HU + jg)*NB + b];
                mhp[i] = xp[(tn*H3 + 2*HU + jg)*NB + b];
            }
        } else {
            #pragma unroll
            for (int i = 0; i < 3; i++) {
                if (i >= nj) break;
                int jg = j0 + jq + 4*i;
                g_y[((tt*2 + dir)*HU + jg)*NB + b] = __uint_as_float(hbv[i]);
            }
        }
    }
}

/* -------- dense1 via tf32 MMA, depth-4 pipeline, single sync/iter -------- */
__global__ void __launch_bounds__(256) dense1_mma(const float* __restrict__ W)
{
    __shared__ __align__(16) float As[4][16][72];
    __shared__ __align__(16) float Ws[4][16][136];
    int n0 = blockIdx.x * 128;
    int kbeg = blockIdx.y * KSEG;
    int tid = threadIdx.x, warp = tid >> 5, lane = tid & 31;
    int g = lane >> 2, tg = lane & 3;
    int wm = (warp >> 2) * 32, wn = (warp & 3) * 32;

    int a_k = tid >> 4, a_m = (tid & 15) * 4;
    int w_k = tid >> 5, w_n = (tid & 31) * 4;
    bool wok = (n0 + w_n) < ND1;

    if (!wok) {
        #pragma unroll
        for (int bf = 0; bf < 4; bf++) {
            *(float4*)&Ws[bf][w_k    ][w_n] = make_float4(0,0,0,0);
            *(float4*)&Ws[bf][w_k + 8][w_n] = make_float4(0,0,0,0);
        }
    }

    float c[2][4][4] = {};

    const int NIT = KSEG / 16;   /* 60 */
    #pragma unroll
    for (int p = 0; p < 3; p++) {
        int k0 = kbeg + p*16;
        cp16(&As[p][a_k][a_m], &g_y[(k0 + a_k)*NB + a_m]);
        if (wok) {
            cp16(&Ws[p][w_k    ][w_n], &W[(size_t)(k0 + w_k    )*ND1 + n0 + w_n]);
            cp16(&Ws[p][w_k + 8][w_n], &W[(size_t)(k0 + w_k + 8)*ND1 + n0 + w_n]);
        }
        cpcommit();
    }

    for (int it = 0; it < NIT; it++) {
        cpwait2();
        __syncthreads();
        int bf = it & 3;
        #pragma unroll
        for (int kh = 0; kh < 2; kh++) {
            int kk = kh * 8;
            unsigned a[2][4], b[4][2];
            #pragma unroll
            for (int mf = 0; mf < 2; mf++) {
                int m = wm + mf*16 + g;
                a[mf][0] = __float_as_uint(As[bf][kk + tg    ][m]);
                a[mf][1] = __float_as_uint(As[bf][kk + tg    ][m + 8]);
                a[mf][2] = __float_as_uint(As[bf][kk + tg + 4][m]);
                a[mf][3] = __float_as_uint(As[bf][kk + tg + 4][m + 8]);
            }
            #pragma unroll
            for (int nf = 0; nf < 4; nf++) {
                int n = wn + nf*8 + g;
                b[nf][0] = tf32r(Ws[bf][kk + tg    ][n]);
                b[nf][1] = tf32r(Ws[bf][kk + tg + 4][n]);
            }
            #pragma unroll
            for (int mf = 0; mf < 2; mf++)
                #pragma unroll
                for (int nf = 0; nf < 4; nf++)
                    mma8(c[mf][nf], a[mf], b[nf]);
        }
        if (it + 3 < NIT) {
            int p = (it + 3) & 3;
            int k0 = kbeg + (it + 3) * 16;
            cp16(&As[p][a_k][a_m], &g_y[(k0 + a_k)*NB + a_m]);
            if (wok) {
                cp16(&Ws[p][w_k    ][w_n], &W[(size_t)(k0 + w_k    )*ND1 + n0 + w_n]);
                cp16(&Ws[p][w_k + 8][w_n], &W[(size_t)(k0 + w_k + 8)*ND1 + n0 + w_n]);
            }
        }
        cpcommit();
    }

    float* dst = g_part[blockIdx.y];
    #pragma unroll
    for (int mf = 0; mf < 2; mf++) {
        #pragma unroll
        for (int nf = 0; nf < 4; nf++) {
            int col = n0 + wn + nf*8 + tg*2;
            if (col < ND1) {
                int r0 = wm + mf*16 + g;
                *(float2*)&dst[r0*ND1 + col]       = make_float2(c[mf][nf][0], c[mf][nf][1]);
                *(float2*)&dst[(r0 + 8)*ND1 + col] = make_float2(c[mf][nf][2], c[mf][nf][3]);
            }
        }
    }
}

__global__ void __launch_bounds__(256) reduce1_kernel(const float* __restrict__ b1)
{
    int i = blockIdx.x * 256 + threadIdx.x;
    if (i >= NB*ND1) return;
    int n = i % ND1;
    float s = b1[n];
    #pragma unroll
    for (int p = 0; p < KSPLIT; p++) s += g_part[p][i];
    g_hidden[i] = fmaxf(s, 0.f);
}

__global__ void __launch_bounds__(320) dense2_kernel(const float* __restrict__ w2,
                                                     const float* __restrict__ b2,
                                                     float* __restrict__ out)
{
    __shared__ float hsh[2*ND1];
    int m0 = blockIdx.x * 2, tid = threadIdx.x;
    for (int i = tid; i < 2*ND1; i += 320) hsh[i] = g_hidden[m0*ND1 + i];
    __syncthreads();
    if (tid >= ND2) return;
    float a0 = 0.f, a1 = 0.f, c0 = 0.f, c1 = 0.f;
    for (int k = 0; k < ND1; k += 2) {
        float w0 = w2[(k    )*ND2 + tid];
        float w1 = w2[(k + 1)*ND2 + tid];
        a0 = fmaf(hsh[k], w0, a0);       a1 = fmaf(hsh[k + 1], w1, a1);
        c0 = fmaf(hsh[ND1 + k], w0, c0); c1 = fmaf(hsh[ND1 + k + 1], w1, c1);
    }
    float bb = b2[tid];
    out[m0*ND2 + tid]       = sigf(a0 + a1 + bb);
    out[(m0 + 1)*ND2 + tid] = sigf(c0 + c1 + bb);
}

extern "C" void kernel_launch(void* const* d_in, const int* in_sizes, int n_in,
                              void* d_out, int out_size)
{
    const float* inputs = (const float*)d_in[0];
    const float* conv_w = (const float*)d_in[1];
    const float* conv_b = (const float*)d_in[2];
    const float* fw_k   = (const float*)d_in[3];
    const float* fw_rk  = (const float*)d_in[4];
    const float* fw_b   = (const float*)d_in[5];
    const float* bw_k   = (const float*)d_in[6];
    const float* bw_rk  = (const float*)d_in[7];
    const float* bw_b   = (const float*)d_in[8];
    const float* w1     = (const float*)d_in[9];
    const float* b1     = (const float*)d_in[10];
    const float* w2     = (const float*)d_in[11];
    const float* b2     = (const float*)d_in[12];
    float* out = (float*)d_out;

    cudaFuncSetAttribute(gru7_kernel, cudaFuncAttributeMaxDynamicSharedMemorySize, GRU7_SMEM);

    conv_mma<<<dim3(FEAT/64, NB), 256>>>(inputs, conv_w, conv_b);
    xproj_mma<<<dim3(TPOOL, H3/64, 2), 256>>>(fw_k, bw_k, fw_b, bw_b);
    gru7_kernel<<<2*GB2, 256, GRU7_SMEM>>>(fw_rk, bw_rk, fw_b, bw_b);
    dense1_mma<<<dim3(16, KSPLIT), 256>>>(w1);
    reduce1_kernel<<<(NB*ND1 + 255)/256, 256>>>(b1);
    dense2_kernel<<<NB/2, 320>>>(w2, b2, out);
}

// round 15
// speedup vs baseline: 1.0607x; 1.0607x over previous
#include <cuda_runtime.h>
#include <math.h>

#define NB 64
#define TIN 1000
#define CIN 4
#define FEAT 320
#define KW 26
#define POOLW 13
#define TPOOL 75
#define HU 320
#define H3 960
#define FLATN 48000
#define ND1 2000
#define ND2 301
#define KSPLIT 75
#define KSEG (FLATN / KSPLIT)   /* 640 */

/* GRU v8: 64 CTAs per dir, 5 units each, rk in registers, 2-level barrier */
#define GB3 64
#define JPC 5
#define PRE_OFF (HU*64)
#define GRU8_SMEM ((HU*64 + 8*16*66) * 4)

#define XSTR 1032

__device__ float g_pooled[NB*TPOOL*FEAT];
__device__ float g_xp[2][TPOOL*H3*NB];
__device__ float g_y[FLATN*NB];
__device__ __align__(128) float g_htf[2][2][HU*NB];
__device__ float g_part[KSPLIT][NB*ND1];
__device__ float g_hidden[NB*ND1];
__device__ unsigned g_cntg[2][8];
__device__ unsigned g_cnt2[2];
__device__ unsigned g_gen2[2];

__device__ __forceinline__ float sigf(float x) { return 1.0f / (1.0f + __expf(-x)); }

__device__ __forceinline__ void cp16(const void* dst, const void* src) {
    unsigned d = (unsigned)__cvta_generic_to_shared(dst);
    asm volatile("cp.async.cg.shared.global [%0], [%1], 16;\n" :: "r"(d), "l"(src));
}
__device__ __forceinline__ void cpcommit() { asm volatile("cp.async.commit_group;\n" ::); }
__device__ __forceinline__ void cpwait0()  { asm volatile("cp.async.wait_group 0;\n" ::); }
__device__ __forceinline__ void cpwait2()  { asm volatile("cp.async.wait_group 2;\n" ::); }
__device__ __forceinline__ unsigned tf32r(float x) {
    unsigned r; asm("cvt.rna.tf32.f32 %0, %1;\n" : "=r"(r) : "f"(x)); return r;
}
__device__ __forceinline__ void mma8(float* c, const unsigned* a, const unsigned* b) {
    asm volatile(
        "mma.sync.aligned.m16n8k8.row.col.f32.tf32.tf32.f32 "
        "{%0,%1,%2,%3},{%4,%5,%6,%7},{%8,%9},{%0,%1,%2,%3};\n"
        : "+f"(c[0]), "+f"(c[1]), "+f"(c[2]), "+f"(c[3])
        : "r"(a[0]), "r"(a[1]), "r"(a[2]), "r"(a[3]), "r"(b[0]), "r"(b[1]));
}
__device__ __forceinline__ int swz(int k, int m) { return k*64 + (m ^ ((k & 3) * 8)); }

/* -------- conv1d + relu + maxpool13 via tf32 MMA (implicit im2col) ------- */
__global__ void __launch_bounds__(256) conv_mma(const float* __restrict__ in,
                                                const float* __restrict__ cw,
                                                const float* __restrict__ cb)
{
    __shared__ __align__(16) float xs[CIN*XSTR];
    __shared__ __align__(16) float Ws[KW*CIN*72];
    int b = blockIdx.y, n0 = blockIdx.x * 64, tid = threadIdx.x;

    for (int i = tid; i < 104*16; i += 256) {
        int kc = i >> 4, nq = (i & 15) * 4;
        cp16(&Ws[kc*72 + nq], &cw[kc*FEAT + n0 + nq]);
    }
    for (int i = tid; i < TIN*CIN; i += 256)
        xs[(i & 3)*XSTR + (i >> 2)] = in[b*TIN*CIN + i];
    if (tid < 4*32) {
        int c = tid >> 5, t = TIN + (tid & 31);
        if (t < XSTR) xs[c*XSTR + t] = 0.f;
    }
    cpcommit(); cpwait0();
    __syncthreads();

    int warp = tid >> 5, lane = tid & 31, g = lane >> 2, tg = lane & 3;
    bool row2ok = (g + 8) < POOLW;

    for (int tp = warp; tp < TPOOL; tp += 8) {
        int t0 = tp * POOLW;
        float c[8][4] = {};
        const float* xrow = &xs[tg*XSTR + t0 + g];
        #pragma unroll
        for (int ks = 0; ks < 13; ks++) {
            unsigned a[4];
            a[0] = tf32r(xrow[2*ks]);
            a[1] = tf32r(xrow[8 + 2*ks]);
            a[2] = tf32r(xrow[2*ks + 1]);
            a[3] = tf32r(xrow[8 + 2*ks + 1]);
            int kk = ks * 8;
            #pragma unroll
            for (int nf = 0; nf < 8; nf++) {
                unsigned bb[2];
                bb[0] = tf32r(Ws[(kk + tg    )*72 + nf*8 + g]);
                bb[1] = tf32r(Ws[(kk + tg + 4)*72 + nf*8 + g]);
                mma8(c[nf], a, bb);
            }
        }
        #pragma unroll
        for (int nf = 0; nf < 8; nf++) {
            float m0 = row2ok ? fmaxf(c[nf][0], c[nf][2]) : c[nf][0];
            float m1 = row2ok ? fmaxf(c[nf][1], c[nf][3]) : c[nf][1];
            #pragma unroll
            for (int off = 4; off < 32; off <<= 1) {
                m0 = fmaxf(m0, __shfl_xor_sync(0xffffffffu, m0, off));
                m1 = fmaxf(m1, __shfl_xor_sync(0xffffffffu, m1, off));
            }
            if (g == 0) {
                int col = n0 + nf*8 + tg*2;
                g_pooled[(b*TPOOL + tp)*FEAT + col]     = fmaxf(m0 + cb[col], 0.f);
                g_pooled[(b*TPOOL + tp)*FEAT + col + 1] = fmaxf(m1 + cb[col + 1], 0.f);
            }
        }
    }
}

/* ------- xproj via tf32 MMA ------- */
__global__ void __launch_bounds__(256) xproj_mma(const float* __restrict__ fwk,
                                                 const float* __restrict__ bwk,
                                                 const float* __restrict__ fwb,
                                                 const float* __restrict__ bwb)
{
    __shared__ __align__(16) float As[2][64][20];
    __shared__ __align__(16) float Ws[2][16][72];
    int m0 = blockIdx.x * 64, n0 = blockIdx.y * 64, dir = blockIdx.z;
    const float* Bk   = dir ? bwk : fwk;
    const float* bias = dir ? bwb : fwb;
    float* xp = g_xp[dir];

    int tid = threadIdx.x, warp = tid >> 5, lane = tid & 31;
    int g = lane >> 2, tg = lane & 3;
    int wm = (warp >> 2) * 32, wn = (warp & 3) * 16;
    int a_m = tid >> 2, a_k = (tid & 3) * 4;
    int w_k = tid >> 4, w_n = (tid & 15) * 4;

    float c[2][2][4] = {};

    cp16(&As[0][a_m][a_k], &g_pooled[(m0 + a_m)*FEAT + a_k]);
    cp16(&Ws[0][w_k][w_n], &Bk[w_k*H3 + n0 + w_n]);
    cpcommit();

    const int NIT = FEAT / 16;
    for (int it = 0; it < NIT; it++) {
        int nb = (it + 1) & 1;
        if (it + 1 < NIT) {
            int k0 = (it + 1) * 16;
            cp16(&As[nb][a_m][a_k], &g_pooled[(m0 + a_m)*FEAT + k0 + a_k]);
            cp16(&Ws[nb][w_k][w_n], &Bk[(k0 + w_k)*H3 + n0 + w_n]);
        }
        cpcommit();
        asm volatile("cp.async.wait_group 1;\n" ::);
        __syncthreads();
        int bf = it & 1;
        #pragma unroll
        for (int kh = 0; kh < 2; kh++) {
            int kk = kh * 8;
            unsigned a[2][4], b[2][2];
            #pragma unroll
            for (int mf = 0; mf < 2; mf++) {
                int m = wm + mf*16 + g;
                a[mf][0] = tf32r(As[bf][m    ][kk + tg]);
                a[mf][1] = tf32r(As[bf][m + 8][kk + tg]);
                a[mf][2] = tf32r(As[bf][m    ][kk + tg + 4]);
                a[mf][3] = tf32r(As[bf][m + 8][kk + tg + 4]);
            }
            #pragma unroll
            for (int nf = 0; nf < 2; nf++) {
                int n = wn + nf*8 + g;
                b[nf][0] = tf32r(Ws[bf][kk + tg    ][n]);
                b[nf][1] = tf32r(Ws[bf][kk + tg + 4][n]);
            }
            #pragma unroll
            for (int mf = 0; mf < 2; mf++)
                #pragma unroll
                for (int nf = 0; nf < 2; nf++)
                    mma8(c[mf][nf], a[mf], b[nf]);
        }
        __syncthreads();
    }

    #pragma unroll
    for (int mf = 0; mf < 2; mf++) {
        #pragma unroll
        for (int nf = 0; nf < 2; nf++) {
            int col = n0 + wn + nf*8 + tg*2;
            float bv0 = bias[col], bv1 = bias[col + 1];
            int r0 = m0 + wm + mf*16 + g;
            int b0 = r0 / TPOOL, t0 = r0 - b0*TPOOL;
            int r1 = r0 + 8;
            int b1 = r1 / TPOOL, t1 = r1 - b1*TPOOL;
            xp[(t0*H3 + col    )*NB + b0] = c[mf][nf][0] + bv0;
            xp[(t0*H3 + col + 1)*NB + b0] = c[mf][nf][1] + bv1;
            xp[(t1*H3 + col    )*NB + b1] = c[mf][nf][2] + bv0;
            xp[(t1*H3 + col + 1)*NB + b1] = c[mf][nf][3] + bv1;
        }
    }
}

/* --- persistent GRU v8: 64 CTAs/dir, 5 units, 2-level barrier ------------ */
__global__ void __launch_bounds__(256, 1) gru8_kernel(
    const float* __restrict__ rk_fw, const float* __restrict__ rk_bw,
    const float* __restrict__ b_fw,  const float* __restrict__ b_bw)
{
    extern __shared__ float smg[];
    float* hs  = smg;                 /* [320][64] tf32 bits, swizzled */
    float* pre = smg + PRE_OFF;       /* [8][16][66] fp32 partials */

    int bx = blockIdx.x, dir = bx >> 6, jb = bx & 63, j0 = jb * JPC;
    const float* rk = dir ? rk_bw : rk_fw;
    const float* br = (dir ? b_bw : b_fw) + H3;
    const float* xp = g_xp[dir];
    int tid = threadIdx.x, warp = tid >> 5, lane = tid & 31;
    int g = lane >> 2, tg = lane & 3;
    int kh = warp * 40;               /* K octile per warp */

    /* prologue: rk slice (cols: z0..4, r0..4, h0..4, pad) as tf32 swizzled */
    for (int i = tid; i < HU*64; i += 256) {
        int k = i >> 6, c = i & 63;
        float v = 0.f;
        if (c < 15) {
            int gi = c / JPC, jj = c - gi*JPC;
            v = rk[k*H3 + gi*HU + j0 + jj];
        }
        hs[swz(k, c)] = __uint_as_float(tf32r(v));
    }
    __syncthreads();

    const unsigned* hsu = (const unsigned*)hs;
    unsigned Bf[5][2][2];
    #pragma unroll
    for (int ks = 0; ks < 5; ks++) {
        int kk = kh + ks*8;
        #pragma unroll
        for (int nf = 0; nf < 2; nf++) {
            int n = nf*8 + g;
            Bf[ks][nf][0] = hsu[swz(kk + tg,     n)];
            Bf[ks][nf][1] = hsu[swz(kk + tg + 4, n)];
        }
    }
    __syncthreads();

    int b = tid & 63, jq = tid >> 6;  /* jq 0..3 */
    int nj = (jq == 0) ? 2 : 1;       /* units: jl = jq (+4 for jq0) */
    float hold[2] = {0.f, 0.f};
    float brz[2], brr[2], brh[2];
    #pragma unroll
    for (int i = 0; i < 2; i++) {
        int jl = jq + 4*i;
        int jg = j0 + ((jl < JPC) ? jl : 0);
        brz[i] = br[jg]; brr[i] = br[HU + jg]; brh[i] = br[2*HU + jg];
    }

    float* buf0 = g_htf[dir][0];
    float* buf1 = g_htf[dir][1];

    float mzp[2], mrp[2], mhp[2];
    {
        int tt0 = dir ? (TPOOL - 1) : 0;
        #pragma unroll
        for (int i = 0; i < 2; i++) {
            int jl = jq + 4*i, jg = j0 + ((jl < JPC) ? jl : 0);
            mzp[i] = xp[(tt0*H3 + jg)*NB + b];
            mrp[i] = xp[(tt0*H3 + HU + jg)*NB + b];
            mhp[i] = xp[(tt0*H3 + 2*HU + jg)*NB + b];
        }
    }
    unsigned mygen = 0;
    unsigned hbv[2] = {0u, 0u};

    for (int s = 0; s < TPOOL; s++) {
        int tt = dir ? (TPOOL - 1 - s) : s;

        if (s > 0) {
            if (tid == 0) {
                while (*((volatile unsigned*)&g_gen2[dir]) == mygen) { }
            }
            __syncthreads();

            const float4* src = (const float4*)((s & 1) ? buf0 : buf1);
            float4* hs4 = (float4*)hs;
            #pragma unroll
            for (int i = 0; i < 20; i++)
                cp16(&hs4[tid + i*256], &src[tid + i*256]);
            cpcommit();
            cpwait0();
            __syncthreads();

            float c[4][2][4] = {};
            #pragma unroll
            for (int ks = 0; ks < 5; ks++) {
                int kk = kh + ks*8;
                unsigned a[4][4];
                #pragma unroll
                for (int mt = 0; mt < 4; mt++) {
                    int m = mt*16;
                    a[mt][0] = hsu[swz(kk + tg,     m + g)];
                    a[mt][1] = hsu[swz(kk + tg,     m + 8 + g)];
                    a[mt][2] = hsu[swz(kk + tg + 4, m + g)];
                    a[mt][3] = hsu[swz(kk + tg + 4, m + 8 + g)];
                }
                #pragma unroll
                for (int mt = 0; mt < 4; mt++)
                    #pragma unroll
                    for (int nf = 0; nf < 2; nf++)
                        mma8(c[mt][nf], a[mt], Bf[ks][nf]);
            }
            float* pb = pre + warp*16*66;
            #pragma unroll
            for (int mt = 0; mt < 4; mt++) {
                #pragma unroll
                for (int nf = 0; nf < 2; nf++) {
                    int n = nf*8 + tg*2;
                    int m = mt*16 + g;
                    pb[(n    )*66 + m]     = c[mt][nf][0];
                    pb[(n + 1)*66 + m]     = c[mt][nf][1];
                    pb[(n    )*66 + m + 8] = c[mt][nf][2];
                    pb[(n + 1)*66 + m + 8] = c[mt][nf][3];
                }
            }
            __syncthreads();
        }

        float* wb = (s & 1) ? buf1 : buf0;
        #pragma unroll
        for (int i = 0; i < 2; i++) {
            if (i >= nj) break;
            int jl = jq + 4*i, jg = j0 + jl;
            float az = 0.f, ar = 0.f, ah = 0.f;
            if (s > 0) {
                #pragma unroll
                for (int p = 0; p < 8; p++) {
                    const float* pb = pre + p*16*66;
                    az += pb[(jl     )*66 + b];
                    ar += pb[(5 + jl )*66 + b];
                    ah += pb[(10 + jl)*66 + b];
                }
            }
            float z    = sigf(mzp[i] + az + brz[i]);
            float r    = sigf(mrp[i] + ar + brr[i]);
            float cand = tanhf(mhp[i] + r * (ah + brh[i]));
            float hn   = z * hold[i] + (1.f - z) * cand;
            hold[i] = hn;
            hbv[i] = tf32r(hn);
            wb[swz(jg, b)] = __uint_as_float(hbv[i]);
        }

        if (s < TPOOL - 1) {
            __threadfence();
            __syncthreads();
            if (tid == 0) {
                mygen = *((volatile unsigned*)&g_gen2[dir]);
                unsigned r = atomicAdd(&g_cntg[dir][jb & 7], 1u);
                if (r == 7u) {
                    unsigned r2 = atomicAdd(&g_cnt2[dir], 1u);
                    if (r2 == 7u) {
                        g_cnt2[dir] = 0u;
                        #pragma unroll
                        for (int i = 0; i < 8; i++) g_cntg[dir][i] = 0u;
                        __threadfence();
                        atomicAdd(&g_gen2[dir], 1u);
                    }
                }
            }
            /* overlap spin: g_y writes + next-step gate prefetch */
            #pragma unroll
            for (int i = 0; i < 2; i++) {
                if (i >= nj) break;
                int jg = j0 + jq + 4*i;
                g_y[((tt*2 + dir)*HU + jg)*NB + b] = __uint_as_float(hbv[i]);
            }
            int tn = dir ? (TPOOL - 2 - s) : (s + 1);
            #pragma unroll
            for (int i = 0; i < 2; i++) {
                int jl = jq + 4*i, jg = j0 + ((jl < JPC) ? jl : 0);
                mzp[i] = xp[(tn*H3 + jg)*NB + b];
                mrp[i] = xp[(tn*H3 + HU + jg)*NB + b];
                mhp[i] = xp[(tn*H3 + 2*HU + jg)*NB + b];
            }
        } else {
            #pragma unroll
            for (int i = 0; i < 2; i++) {
                if (i >= nj) break;
                int jg = j0 + jq + 4*i;
                g_y[((tt*2 + dir)*HU + jg)*NB + b] = __uint_as_float(hbv[i]);
            }
        }
    }
}

/* -------- dense1 via tf32 MMA, depth-4 pipeline, single sync/iter -------- */
__global__ void __launch_bounds__(256) dense1_mma(const float* __restrict__ W)
{
    __shared__ __align__(16) float As[4][16][72];
    __shared__ __align__(16) float Ws[4][16][136];
    int n0 = blockIdx.x * 128;
    int kbeg = blockIdx.y * KSEG;
    int tid = threadIdx.x, warp = tid >> 5, lane = tid & 31;
    int g = lane >> 2, tg = lane & 3;
    int wm = (warp >> 2) * 32, wn = (warp & 3) * 32;

    int a_k = tid >> 4, a_m = (tid & 15) * 4;
    int w_k = tid >> 5, w_n = (tid & 31) * 4;
    bool wok = (n0 + w_n) < ND1;

    if (!wok) {
        #pragma unroll
        for (int bf = 0; bf < 4; bf++) {
            *(float4*)&Ws[bf][w_k    ][w_n] = make_float4(0,0,0,0);
            *(float4*)&Ws[bf][w_k + 8][w_n] = make_float4(0,0,0,0);
        }
    }

    float c[2][4][4] = {};

    const int NIT = KSEG / 16;   /* 40 */
    #pragma unroll
    for (int p = 0; p < 3; p++) {
        int k0 = kbeg + p*16;
        cp16(&As[p][a_k][a_m], &g_y[(k0 + a_k)*NB + a_m]);
        if (wok) {
            cp16(&Ws[p][w_k    ][w_n], &W[(size_t)(k0 + w_k    )*ND1 + n0 + w_n]);
            cp16(&Ws[p][w_k + 8][w_n], &W[(size_t)(k0 + w_k + 8)*ND1 + n0 + w_n]);
        }
        cpcommit();
    }

    for (int it = 0; it < NIT; it++) {
        cpwait2();
        __syncthreads();
        int bf = it & 3;
        #pragma unroll
        for (int kh = 0; kh < 2; kh++) {
            int kk = kh * 8;
            unsigned a[2][4], b[4][2];
            #pragma unroll
            for (int mf = 0; mf < 2; mf++) {
                int m = wm + mf*16 + g;
                a[mf][0] = __float_as_uint(As[bf][kk + tg    ][m]);
                a[mf][1] = __float_as_uint(As[bf][kk + tg    ][m + 8]);
                a[mf][2] = __float_as_uint(As[bf][kk + tg + 4][m]);
                a[mf][3] = __float_as_uint(As[bf][kk + tg + 4][m + 8]);
            }
            #pragma unroll
            for (int nf = 0; nf < 4; nf++) {
                int n = wn + nf*8 + g;
                b[nf][0] = tf32r(Ws[bf][kk + tg    ][n]);
                b[nf][1] = tf32r(Ws[bf][kk + tg + 4][n]);
            }
            #pragma unroll
            for (int mf = 0; mf < 2; mf++)
                #pragma unroll
                for (int nf = 0; nf < 4; nf++)
                    mma8(c[mf][nf], a[mf], b[nf]);
        }
        if (it + 3 < NIT) {
            int p = (it + 3) & 3;
            int k0 = kbeg + (it + 3) * 16;
            cp16(&As[p][a_k][a_m], &g_y[(k0 + a_k)*NB + a_m]);
            if (wok) {
                cp16(&Ws[p][w_k    ][w_n], &W[(size_t)(k0 + w_k    )*ND1 + n0 + w_n]);
                cp16(&Ws[p][w_k + 8][w_n], &W[(size_t)(k0 + w_k + 8)*ND1 + n0 + w_n]);
            }
        }
        cpcommit();
    }

    float* dst = g_part[blockIdx.y];
    #pragma unroll
    for (int mf = 0; mf < 2; mf++) {
        #pragma unroll
        for (int nf = 0; nf < 4; nf++) {
            int col = n0 + wn + nf*8 + tg*2;
            if (col < ND1) {
                int r0 = wm + mf*16 + g;
                *(float2*)&dst[r0*ND1 + col]       = make_float2(c[mf][nf][0], c[mf][nf][1]);
                *(float2*)&dst[(r0 + 8)*ND1 + col] = make_float2(c[mf][nf][2], c[mf][nf][3]);
            }
        }
    }
}

__global__ void __launch_bounds__(256) reduce1_kernel(const float* __restrict__ b1)
{
    int i = blockIdx.x * 256 + threadIdx.x;
    if (i >= NB*ND1) return;
    int n = i % ND1;
    float s = b1[n];
    #pragma unroll
    for (int p = 0; p < KSPLIT; p++) s += g_part[p][i];
    g_hidden[i] = fmaxf(s, 0.f);
}

__global__ void __launch_bounds__(320) dense2_kernel(const float* __restrict__ w2,
                                                     const float* __restrict__ b2,
                                                     float* __restrict__ out)
{
    __shared__ float hsh[2*ND1];
    int m0 = blockIdx.x * 2, tid = threadIdx.x;
    for (int i = tid; i < 2*ND1; i += 320) hsh[i] = g_hidden[m0*ND1 + i];
    __syncthreads();
    if (tid >= ND2) return;
    float a0 = 0.f, a1 = 0.f, c0 = 0.f, c1 = 0.f;
    for (int k = 0; k < ND1; k += 2) {
        float w0 = w2[(k    )*ND2 + tid];
        float w1 = w2[(k + 1)*ND2 + tid];
        a0 = fmaf(hsh[k], w0, a0);       a1 = fmaf(hsh[k + 1], w1, a1);
        c0 = fmaf(hsh[ND1 + k], w0, c0); c1 = fmaf(hsh[ND1 + k + 1], w1, c1);
    }
    float bb = b2[tid];
    out[m0*ND2 + tid]       = sigf(a0 + a1 + bb);
    out[(m0 + 1)*ND2 + tid] = sigf(c0 + c1 + bb);
}

extern "C" void kernel_launch(void* const* d_in, const int* in_sizes, int n_in,
                              void* d_out, int out_size)
{
    const float* inputs = (const float*)d_in[0];
    const float* conv_w = (const float*)d_in[1];
    const float* conv_b = (const float*)d_in[2];
    const float* fw_k   = (const float*)d_in[3];
    const float* fw_rk  = (const float*)d_in[4];
    const float* fw_b   = (const float*)d_in[5];
    const float* bw_k   = (const float*)d_in[6];
    const float* bw_rk  = (const float*)d_in[7];
    const float* bw_b   = (const float*)d_in[8];
    const float* w1     = (const float*)d_in[9];
    const float* b1     = (const float*)d_in[10];
    const float* w2     = (const float*)d_in[11];
    const float* b2     = (const float*)d_in[12];
    float* out = (float*)d_out;

    cudaFuncSetAttribute(gru8_kernel, cudaFuncAttributeMaxDynamicSharedMemorySize, GRU8_SMEM);

    conv_mma<<<dim3(FEAT/64, NB), 256>>>(inputs, conv_w, conv_b);
    xproj_mma<<<dim3(TPOOL, H3/64, 2), 256>>>(fw_k, bw_k, fw_b, bw_b);
    gru8_kernel<<<2*GB3, 256, GRU8_SMEM>>>(fw_rk, bw_rk, fw_b, bw_b);
    dense1_mma<<<dim3(16, KSPLIT), 256>>>(w1);
    reduce1_kernel<<<(NB*ND1 + 255)/256, 256>>>(b1);
    dense2_kernel<<<NB/2, 320>>>(w2, b2, out);
}